// round 13
// baseline (speedup 1.0000x reference)
#include <cuda_runtime.h>
#include <cuda_bf16.h>
#include <math.h>

// Problem constants: x(B,T,C), W_attn(C,3C), b_attn(3C), W_proj(C,C), b_proj(C), route(H,T)
#define BATCH 2
#define SEQ   2048
#define CH    2048
#define NH    16
#define HD    128
#define KSEL  64
#define MROWS (BATCH*SEQ)      // 4096
#define C3    (3*CH)           // 6144

// ---------------------------------------------------------------------------
// Scratch (device globals; no allocations allowed)
// ---------------------------------------------------------------------------
__device__ float g_qkv [MROWS * C3];            // qkv after GEMM1 (+RoPE in place)
__device__ int   g_order[NH * SEQ];             // per-head sorted indices
__device__ int   g_sel  [NH * SEQ * KSEL];      // per (h,t) selected keys
__device__ float2 g_trig[SEQ * (HD / 2)];       // (cos,sin) per (t, freq)

// bf16 hi/lo splits
__device__ __nv_bfloat16 g_xh [MROWS * CH];
__device__ __nv_bfloat16 g_xl [MROWS * CH];
__device__ __nv_bfloat16 g_wah[CH * C3];
__device__ __nv_bfloat16 g_wal[CH * C3];
__device__ __nv_bfloat16 g_wph[CH * CH];
__device__ __nv_bfloat16 g_wpl[CH * CH];
__device__ __nv_bfloat16 g_ah [MROWS * CH];     // attention output hi
__device__ __nv_bfloat16 g_al [MROWS * CH];     // attention output lo

// ---------------------------------------------------------------------------
// PTX helpers
// ---------------------------------------------------------------------------
__device__ __forceinline__ void ldsm_x4(unsigned* r, unsigned addr) {
    asm volatile("ldmatrix.sync.aligned.m8n8.x4.shared.b16 {%0,%1,%2,%3}, [%4];"
                 : "=r"(r[0]), "=r"(r[1]), "=r"(r[2]), "=r"(r[3]) : "r"(addr));
}
__device__ __forceinline__ void ldsm_x2t(unsigned* r, unsigned addr) {
    asm volatile("ldmatrix.sync.aligned.m8n8.x2.trans.shared.b16 {%0,%1}, [%2];"
                 : "=r"(r[0]), "=r"(r[1]) : "r"(addr));
}
__device__ __forceinline__ void mma16816(float* c, const unsigned* a, const unsigned* b) {
    asm volatile("mma.sync.aligned.m16n8k16.row.col.f32.bf16.bf16.f32 "
                 "{%0,%1,%2,%3}, {%4,%5,%6,%7}, {%8,%9}, {%0,%1,%2,%3};"
                 : "+f"(c[0]), "+f"(c[1]), "+f"(c[2]), "+f"(c[3])
                 : "r"(a[0]), "r"(a[1]), "r"(a[2]), "r"(a[3]),
                   "r"(b[0]), "r"(b[1]));
}
__device__ __forceinline__ void cpasync16(unsigned dst, const void* src) {
    asm volatile("cp.async.cg.shared.global [%0], [%1], 16;" :: "r"(dst), "l"(src));
}
__device__ __forceinline__ void cp_commit() { asm volatile("cp.async.commit_group;"); }
template <int N> __device__ __forceinline__ void cp_wait() {
    asm volatile("cp.async.wait_group %0;" :: "n"(N));
}

// ---------------------------------------------------------------------------
// Split fp32 -> (hi, lo) bf16, vectorized: 4 elements / thread.
// n must be a multiple of 4 (all our sizes are).
// ---------------------------------------------------------------------------
__global__ void split_kernel(const float* __restrict__ src,
                             __nv_bfloat16* __restrict__ hi,
                             __nv_bfloat16* __restrict__ lo, int n)
{
    int i4 = blockIdx.x * blockDim.x + threadIdx.x;
    if (i4 * 4 >= n) return;
    float4 v = *(const float4*)(src + i4 * 4);

    __nv_bfloat16 h0 = __float2bfloat16(v.x);
    __nv_bfloat16 h1 = __float2bfloat16(v.y);
    __nv_bfloat16 h2 = __float2bfloat16(v.z);
    __nv_bfloat16 h3 = __float2bfloat16(v.w);
    __nv_bfloat162* hp = (__nv_bfloat162*)(hi + i4 * 4);
    hp[0] = __nv_bfloat162(h0, h1);
    hp[1] = __nv_bfloat162(h2, h3);

    __nv_bfloat16 l0 = __float2bfloat16(v.x - __bfloat162float(h0));
    __nv_bfloat16 l1 = __float2bfloat16(v.y - __bfloat162float(h1));
    __nv_bfloat16 l2 = __float2bfloat16(v.z - __bfloat162float(h2));
    __nv_bfloat16 l3 = __float2bfloat16(v.w - __bfloat162float(h3));
    __nv_bfloat162* lp = (__nv_bfloat162*)(lo + i4 * 4);
    lp[0] = __nv_bfloat162(l0, l1);
    lp[1] = __nv_bfloat162(l2, l3);
}

// ---------------------------------------------------------------------------
// 3xBF16 split GEMM: C = A(MxK)@B(KxN) + bias, fp32 out.
// A given as hi/lo bf16 [M][K]; B as hi/lo bf16 [K][N]. Tiles 128x128x32,
// 256 threads (8 warps = 2m x 4n, 64x32 warp tiles), cp.async double buffer.
// ---------------------------------------------------------------------------
#define PA_B 80    // A smem row pitch bytes (40 bf16): 16B-aligned, LDSM conflict-free
#define PB_B 272   // B smem row pitch bytes (136 bf16)
#define ASPLIT_SZ 10240   // 128*80 per buffer
#define BSPLIT_SZ 8704    // 32*272 per buffer
#define SM_AH 0
#define SM_AL (2*ASPLIT_SZ)                 // 20480
#define SM_BH (4*ASPLIT_SZ)                 // 40960
#define SM_BL (4*ASPLIT_SZ + 2*BSPLIT_SZ)   // 58368
#define SM_TOTAL (4*ASPLIT_SZ + 4*BSPLIT_SZ) // 75776

__global__ __launch_bounds__(256)
void sgemm3x(const __nv_bfloat16* __restrict__ Ah, const __nv_bfloat16* __restrict__ Al,
             const __nv_bfloat16* __restrict__ Bh, const __nv_bfloat16* __restrict__ Bl,
             const float* __restrict__ bias, float* __restrict__ Cmat,
             int M, int N, int K)
{
    extern __shared__ char smem[];
    const unsigned sbase = (unsigned)__cvta_generic_to_shared(smem);

    const int tid  = threadIdx.x;
    const int lane = tid & 31;
    const int wid  = tid >> 5;
    const int wm   = wid & 1;          // 0..1 -> m offset wm*64
    const int wn   = wid >> 1;         // 0..3 -> n offset wn*32
    const int bx = blockIdx.x, by = blockIdx.y;
    const int nt = K >> 5;             // BK=32 tiles

    float acc[4][4][4];
#pragma unroll
    for (int mi = 0; mi < 4; mi++)
#pragma unroll
        for (int ni = 0; ni < 4; ni++)
#pragma unroll
            for (int r = 0; r < 4; r++) acc[mi][ni][r] = 0.0f;

    // cp.async tile loader
    auto issue = [&](int kt, int buf) {
        // A: 512 16B chunks per split (128 rows x 4 chunks)
        const unsigned dAH = sbase + SM_AH + buf * ASPLIT_SZ;
        const unsigned dAL = sbase + SM_AL + buf * ASPLIT_SZ;
#pragma unroll
        for (int i = 0; i < 2; i++) {
            int lin = tid + i * 256;            // 0..511
            int m = lin >> 2, k8 = (lin & 3) << 3;
            size_t go = (size_t)(by * 128 + m) * K + kt * 32 + k8;
            unsigned so = m * PA_B + k8 * 2;
            cpasync16(dAH + so, Ah + go);
            cpasync16(dAL + so, Al + go);
        }
        // B: 512 16B chunks per split (32 rows x 16 chunks)
        const unsigned dBH = sbase + SM_BH + buf * BSPLIT_SZ;
        const unsigned dBL = sbase + SM_BL + buf * BSPLIT_SZ;
#pragma unroll
        for (int i = 0; i < 2; i++) {
            int lin = tid + i * 256;
            int k = lin >> 4, n8 = (lin & 15) << 3;
            size_t go = (size_t)(kt * 32 + k) * N + bx * 128 + n8;
            unsigned so = k * PB_B + n8 * 2;
            cpasync16(dBH + so, Bh + go);
            cpasync16(dBL + so, Bl + go);
        }
    };

    issue(0, 0);
    cp_commit();

    // per-lane fragment address components
    const int a_row = lane & 15;               // row within 16-row subtile
    const int a_half = (lane >> 4) & 1;        // k half (0 or 8)
    const int b_krow = lane & 15;              // k row within 16

    for (int kt = 0; kt < nt; kt++) {
        if (kt + 1 < nt) { issue(kt + 1, (kt + 1) & 1); cp_commit(); }
        if (kt + 1 < nt) cp_wait<1>(); else cp_wait<0>();
        __syncthreads();

        const int buf = kt & 1;
        const unsigned sAH = sbase + SM_AH + buf * ASPLIT_SZ;
        const unsigned sBH = sbase + SM_BH + buf * BSPLIT_SZ;

#pragma unroll
        for (int ks = 0; ks < 2; ks++) {
            unsigned aH[4][4], aL[4][4], bH[4][2], bL[4][2];
#pragma unroll
            for (int mi = 0; mi < 4; mi++) {
                unsigned ad = sAH + (wm * 64 + mi * 16 + a_row) * PA_B
                                  + (ks * 16 + a_half * 8) * 2;
                ldsm_x4(aH[mi], ad);
                ldsm_x4(aL[mi], ad + (SM_AL - SM_AH));
            }
#pragma unroll
            for (int ni = 0; ni < 4; ni++) {
                unsigned bd = sBH + (ks * 16 + b_krow) * PB_B
                                  + (wn * 32 + ni * 8) * 2;
                ldsm_x2t(bH[ni], bd);
                ldsm_x2t(bL[ni], bd + (SM_BL - SM_BH));
            }
#pragma unroll
            for (int mi = 0; mi < 4; mi++)
#pragma unroll
                for (int ni = 0; ni < 4; ni++) {
                    mma16816(acc[mi][ni], aH[mi], bH[ni]);
                    mma16816(acc[mi][ni], aH[mi], bL[ni]);
                    mma16816(acc[mi][ni], aL[mi], bH[ni]);
                }
        }
        __syncthreads();
    }

    // epilogue: c0,c1 -> (row g, cols 2t,2t+1); c2,c3 -> (row g+8)
    const int g  = lane >> 2;
    const int tg = lane & 3;
#pragma unroll
    for (int ni = 0; ni < 4; ni++) {
        int col = bx * 128 + wn * 32 + ni * 8 + tg * 2;
        float2 bb = *(const float2*)(bias + col);
#pragma unroll
        for (int mi = 0; mi < 4; mi++) {
            int row = by * 128 + wm * 64 + mi * 16 + g;
            float2 v0 = make_float2(acc[mi][ni][0] + bb.x, acc[mi][ni][1] + bb.y);
            float2 v1 = make_float2(acc[mi][ni][2] + bb.x, acc[mi][ni][3] + bb.y);
            *(float2*)(Cmat + (size_t)row * N + col)       = v0;
            *(float2*)(Cmat + (size_t)(row + 8) * N + col) = v1;
        }
    }
}

// ---------------------------------------------------------------------------
// Fill (cos,sin) table for (t, i): 131072 entries, double-precision trig once.
// Angle computed as fp32 t*freq to match the reference's rounding.
// ---------------------------------------------------------------------------
__global__ void trig_table_kernel()
{
    int idx = blockIdx.x * blockDim.x + threadIdx.x;
    if (idx >= SEQ * (HD / 2)) return;
    int i = idx & 63;             // freq index
    int t = idx >> 6;             // position

    float fr  = (float)exp(-(double)i * (9.210340371976184 / 64.0)); // ln(1e4)/64
    float ang = (float)t * fr;    // fp32 rounding like reference
    g_trig[idx] = make_float2((float)cos((double)ang), (float)sin((double)ang));
}

// ---------------------------------------------------------------------------
// RoPE in-place on q and k halves of g_qkv, reading the trig table.
// ---------------------------------------------------------------------------
__global__ void rope_kernel()
{
    int idx = blockIdx.x * blockDim.x + threadIdx.x;
    if (idx >= BATCH * SEQ * NH * (HD / 2)) return;
    int i  = idx & 63;
    int h  = (idx >> 6) & (NH - 1);
    int bt = idx >> 10;
    int t  = bt & (SEQ - 1);

    float2 cs = g_trig[t * 64 + i];
    float c = cs.x, s = cs.y;

    size_t base = (size_t)bt * C3 + h * HD + 2 * i;
    float e, o;
    e = g_qkv[base];     o = g_qkv[base + 1];
    g_qkv[base]     = e * c - o * s;
    g_qkv[base + 1] = e * s + o * c;
    e = g_qkv[base + CH]; o = g_qkv[base + CH + 1];
    g_qkv[base + CH]     = e * c - o * s;
    g_qkv[base + CH + 1] = e * s + o * c;
}

// ---------------------------------------------------------------------------
// Per-head bitonic sort of route weights by (w desc, idx asc)
// ---------------------------------------------------------------------------
__global__ void sort_routes_kernel(const float* __restrict__ rw)
{
    __shared__ unsigned long long key[SEQ];
    int h = blockIdx.x;
    int tid = threadIdx.x;

    for (int i = tid; i < SEQ; i += 1024) {
        unsigned uw = __float_as_uint(rw[h * SEQ + i]);
        uw = (uw & 0x80000000u) ? ~uw : (uw | 0x80000000u);
        key[i] = ((unsigned long long)(~uw) << 32) | (unsigned)i;
    }
    __syncthreads();

    for (int k = 2; k <= SEQ; k <<= 1) {
        for (int j = k >> 1; j > 0; j >>= 1) {
#pragma unroll 1
            for (int base = 0; base < SEQ; base += 1024) {
                int i = base + tid;
                int ixj = i ^ j;
                if (ixj > i) {
                    bool up = ((i & k) == 0);
                    unsigned long long a = key[i], b = key[ixj];
                    if ((a > b) == up) { key[i] = b; key[ixj] = a; }
                }
            }
            __syncthreads();
        }
    }
    for (int i = tid; i < SEQ; i += 1024)
        g_order[h * SEQ + i] = (int)(key[i] & 0xFFFFFFFFu);
}

// ---------------------------------------------------------------------------
// Per (h,t): first min(t+1,64) sorted entries with idx <= t
// ---------------------------------------------------------------------------
__global__ void select_kernel()
{
    int w    = (blockIdx.x << 3) + (threadIdx.x >> 5);
    int lane = threadIdx.x & 31;
    int h = w >> 11;
    int t = w & (SEQ - 1);
    int cnt = min(t + 1, KSEL);
    const int* ord = g_order + h * SEQ;
    int* sel = g_sel + (size_t)w * KSEL;

    int collected = 0, base = 0;
    while (collected < cnt && base < SEQ) {
        int v = ord[base + lane];
        bool f = (v <= t);
        unsigned bal = __ballot_sync(0xffffffffu, f);
        int pos = collected + __popc(bal & ((1u << lane) - 1u));
        if (f && pos < cnt) sel[pos] = v;
        collected += __popc(bal);
        base += 32;
    }
}

// ---------------------------------------------------------------------------
// Sparse attention: one warp per (b,h,t); output written pre-split (hi/lo)
// ---------------------------------------------------------------------------
__global__ void attn_kernel()
{
    int w    = (blockIdx.x << 3) + (threadIdx.x >> 5);
    int lane = threadIdx.x & 31;
    int b   = w >> 15;
    int rem = w & (NH * SEQ - 1);
    int h   = rem >> 11;
    int t   = rem & (SEQ - 1);
    int cnt = min(t + 1, KSEL);

    const float* qp = g_qkv + (size_t)(b * SEQ + t) * C3 + h * HD;
    float4 q = *(const float4*)(qp + lane * 4);

    const int* sel = g_sel + (size_t)(h * SEQ + t) * KSEL;
    int jA = (lane < cnt)      ? sel[lane]      : 0;
    int jB = (32 + lane < cnt) ? sel[32 + lane] : 0;

    const float* kbase = g_qkv + (size_t)b * SEQ * C3 + CH     + h * HD;
    const float* vbase = g_qkv + (size_t)b * SEQ * C3 + 2 * CH + h * HD;

    float s0 = -INFINITY, s1 = -INFINITY;
    for (int kk = 0; kk < cnt; kk++) {
        int j = __shfl_sync(0xffffffffu, (kk & 32) ? jB : jA, kk & 31);
        float4 kv = *(const float4*)(kbase + (size_t)j * C3 + lane * 4);
        float p = q.x * kv.x + q.y * kv.y + q.z * kv.z + q.w * kv.w;
#pragma unroll
        for (int o = 16; o > 0; o >>= 1) p += __shfl_xor_sync(0xffffffffu, p, o);
        p *= 0.08838834764831845f;  // 1/sqrt(128)
        if (kk < 32) { if (lane == kk)      s0 = p; }
        else         { if (lane == kk - 32) s1 = p; }
    }

    float m = fmaxf(s0, s1);
#pragma unroll
    for (int o = 16; o > 0; o >>= 1) m = fmaxf(m, __shfl_xor_sync(0xffffffffu, m, o));
    float p0 = (s0 == -INFINITY) ? 0.0f : expf(s0 - m);
    float p1 = (s1 == -INFINITY) ? 0.0f : expf(s1 - m);
    float sum = p0 + p1;
#pragma unroll
    for (int o = 16; o > 0; o >>= 1) sum += __shfl_xor_sync(0xffffffffu, sum, o);
    float inv = 1.0f / sum;
    p0 *= inv; p1 *= inv;

    float4 acc = make_float4(0.f, 0.f, 0.f, 0.f);
    for (int kk = 0; kk < cnt; kk++) {
        int   j = __shfl_sync(0xffffffffu, (kk & 32) ? jB : jA, kk & 31);
        float p = __shfl_sync(0xffffffffu, (kk & 32) ? p1 : p0, kk & 31);
        float4 vv = *(const float4*)(vbase + (size_t)j * C3 + lane * 4);
        acc.x += p * vv.x; acc.y += p * vv.y; acc.z += p * vv.z; acc.w += p * vv.w;
    }

    size_t ob = (size_t)(b * SEQ + t) * CH + h * HD + lane * 4;
    float vv[4] = {acc.x, acc.y, acc.z, acc.w};
#pragma unroll
    for (int i = 0; i < 4; i++) {
        __nv_bfloat16 hv = __float2bfloat16(vv[i]);
        g_ah[ob + i] = hv;
        g_al[ob + i] = __float2bfloat16(vv[i] - __bfloat162float(hv));
    }
}

// ---------------------------------------------------------------------------
extern "C" void kernel_launch(void* const* d_in, const int* in_sizes, int n_in,
                              void* d_out, int out_size)
{
    const float* x      = (const float*)d_in[0];
    const float* W_attn = (const float*)d_in[1];
    const float* b_attn = (const float*)d_in[2];
    const float* W_proj = (const float*)d_in[3];
    const float* b_proj = (const float*)d_in[4];
    const float* route  = (const float*)d_in[5];
    float* out = (float*)d_out;

    void* p;
    cudaGetSymbolAddress(&p, g_xh);  __nv_bfloat16* xh  = (__nv_bfloat16*)p;
    cudaGetSymbolAddress(&p, g_xl);  __nv_bfloat16* xl  = (__nv_bfloat16*)p;
    cudaGetSymbolAddress(&p, g_wah); __nv_bfloat16* wah = (__nv_bfloat16*)p;
    cudaGetSymbolAddress(&p, g_wal); __nv_bfloat16* wal = (__nv_bfloat16*)p;
    cudaGetSymbolAddress(&p, g_wph); __nv_bfloat16* wph = (__nv_bfloat16*)p;
    cudaGetSymbolAddress(&p, g_wpl); __nv_bfloat16* wpl = (__nv_bfloat16*)p;
    cudaGetSymbolAddress(&p, g_ah);  __nv_bfloat16* ah  = (__nv_bfloat16*)p;
    cudaGetSymbolAddress(&p, g_al);  __nv_bfloat16* al  = (__nv_bfloat16*)p;
    cudaGetSymbolAddress(&p, g_qkv); float* qkv = (float*)p;

    // Unconditional (no static guards — harness rule). Idempotent + capture-safe.
    cudaFuncSetAttribute(sgemm3x, cudaFuncAttributeMaxDynamicSharedMemorySize,
                         SM_TOTAL);

    // 0) split inputs to bf16 hi/lo (4 elems/thread) + trig table
    split_kernel<<<(MROWS * CH / 4 + 255) / 256, 256>>>(x, xh, xl, MROWS * CH);
    split_kernel<<<(CH * C3 / 4 + 255) / 256, 256>>>(W_attn, wah, wal, CH * C3);
    split_kernel<<<(CH * CH / 4 + 255) / 256, 256>>>(W_proj, wph, wpl, CH * CH);
    trig_table_kernel<<<(SEQ * (HD / 2) + 255) / 256, 256>>>();

    // 1) qkv = x @ W_attn + b_attn
    sgemm3x<<<dim3(C3 / 128, MROWS / 128), 256, SM_TOTAL>>>(
        xh, xl, wah, wal, b_attn, qkv, MROWS, C3, CH);

    // 2) RoPE on q,k in place (table lookup)
    rope_kernel<<<(BATCH * SEQ * NH * (HD / 2) + 255) / 256, 256>>>();

    // 3) per-head route-weight argsort
    sort_routes_kernel<<<NH, 1024>>>(route);

    // 4) per-(h,t) top-64 prefix selection
    select_kernel<<<(NH * SEQ) / 8, 256>>>();

    // 5) sparse attention (writes hi/lo split directly)
    attn_kernel<<<(BATCH * NH * SEQ) / 8, 256>>>();

    // 6) out = attn @ W_proj + b_proj
    sgemm3x<<<dim3(CH / 128, MROWS / 128), 256, SM_TOTAL>>>(
        ah, al, wph, wpl, b_proj, out, MROWS, CH, CH);
}